// round 1
// baseline (speedup 1.0000x reference)
#include <cuda_runtime.h>
#include <math.h>

#define HID 128
#define NB 32
#define KIN (2*HID + NB)   // 288
#define TILE_E 8           // edges per warp
#define WARPS 4
#define MAX_NODES 50000
#define FULL 0xffffffffu

// Scratch (allocation-free rule: static __device__ globals)
__device__ float g_acc[(size_t)MAX_NODES * HID];
__device__ float g_deg[MAX_NODES];

__global__ void zero_kernel(int n_nodes) {
    int tid = blockIdx.x * blockDim.x + threadIdx.x;
    int stride = gridDim.x * blockDim.x;
    int tot = n_nodes * HID;
    for (int i = tid; i < tot; i += stride) g_acc[i] = 0.0f;
    for (int i = tid; i < n_nodes; i += stride) g_deg[i] = 0.0f;
}

__global__ __launch_bounds__(128)
void edge_kernel(const float* __restrict__ feat, const float* __restrict__ pos,
                 const int* __restrict__ ei,
                 const float* __restrict__ W1, const float* __restrict__ b1,
                 const float* __restrict__ W2, const float* __restrict__ b2,
                 int E)
{
    __shared__ float smem[WARPS][TILE_E][KIN];   // 36864 B
    const int warp = threadIdx.x >> 5;
    const int lane = threadIdx.x & 31;
    const int ebase = blockIdx.x * (WARPS * TILE_E) + warp * TILE_E;
    float (*msg)[KIN] = smem[warp];

    // ---- per-edge metadata (lanes 0..7 own one edge each) ----
    int my_src = 0, my_dst = 0;
    float my_d = 0.0f;
    int my_valid = 0;
    if (lane < TILE_E) {
        int e = ebase + lane;
        if (e < E) {
            my_valid = 1;
            my_src = ei[e];
            my_dst = ei[E + e];
            float dx = pos[3*my_dst+0] - pos[3*my_src+0];
            float dy = pos[3*my_dst+1] - pos[3*my_src+1];
            float dz = pos[3*my_dst+2] - pos[3*my_src+2];
            float dist = sqrtf(dx*dx + dy*dy + dz*dz);
            my_d = fminf(dist, 5.0f);
            atomicAdd(&g_deg[my_dst], 1.0f);
        }
    }

    const float step   = 5.0f / (float)(NB - 1);
    const float inv_w  = 1.0f / (0.5f * (step + 0.01f));
    const float center = (float)lane * step;

    // ---- stage msg tile: [src feats | dst feats | rbf] ----
    #pragma unroll
    for (int e = 0; e < TILE_E; e++) {
        int s    = __shfl_sync(FULL, my_src, e);
        int d    = __shfl_sync(FULL, my_dst, e);
        float dd = __shfl_sync(FULL, my_d,   e);
        float4 fs = *(const float4*)(feat + (size_t)s * HID + 4*lane);
        float4 fd = *(const float4*)(feat + (size_t)d * HID + 4*lane);
        *(float4*)(&msg[e][4*lane])       = fs;
        *(float4*)(&msg[e][HID + 4*lane]) = fd;
        float t = (dd - center) * inv_w;
        msg[e][2*HID + lane] = __expf(-0.5f * t * t);
    }
    __syncwarp();

    // ---- layer 1: [8,288] @ [288,128]; lane owns 4 cols ----
    float acc[TILE_E][4];
    {
        float4 bb = *(const float4*)(b1 + 4*lane);
        #pragma unroll
        for (int e = 0; e < TILE_E; e++) {
            acc[e][0] = bb.x; acc[e][1] = bb.y; acc[e][2] = bb.z; acc[e][3] = bb.w;
        }
    }
    #pragma unroll 4
    for (int k = 0; k < KIN; k++) {
        float4 w = *(const float4*)(W1 + (size_t)k * HID + 4*lane);
        #pragma unroll
        for (int e = 0; e < TILE_E; e++) {
            float m = msg[e][k];
            acc[e][0] = fmaf(m, w.x, acc[e][0]);
            acc[e][1] = fmaf(m, w.y, acc[e][1]);
            acc[e][2] = fmaf(m, w.z, acc[e][2]);
            acc[e][3] = fmaf(m, w.w, acc[e][3]);
        }
    }
    __syncwarp();

    // ---- SiLU, transpose through smem (reuse first 128 cols) ----
    #pragma unroll
    for (int e = 0; e < TILE_E; e++) {
        float4 s;
        s.x = acc[e][0] / (1.0f + __expf(-acc[e][0]));
        s.y = acc[e][1] / (1.0f + __expf(-acc[e][1]));
        s.z = acc[e][2] / (1.0f + __expf(-acc[e][2]));
        s.w = acc[e][3] / (1.0f + __expf(-acc[e][3]));
        *(float4*)(&msg[e][4*lane]) = s;
    }
    __syncwarp();

    // ---- layer 2: [8,128] @ [128,128] ----
    float acc2[TILE_E][4];
    {
        float4 bb = *(const float4*)(b2 + 4*lane);
        #pragma unroll
        for (int e = 0; e < TILE_E; e++) {
            acc2[e][0] = bb.x; acc2[e][1] = bb.y; acc2[e][2] = bb.z; acc2[e][3] = bb.w;
        }
    }
    #pragma unroll 4
    for (int k = 0; k < HID; k++) {
        float4 w = *(const float4*)(W2 + (size_t)k * HID + 4*lane);
        #pragma unroll
        for (int e = 0; e < TILE_E; e++) {
            float m = msg[e][k];
            acc2[e][0] = fmaf(m, w.x, acc2[e][0]);
            acc2[e][1] = fmaf(m, w.y, acc2[e][1]);
            acc2[e][2] = fmaf(m, w.z, acc2[e][2]);
            acc2[e][3] = fmaf(m, w.w, acc2[e][3]);
        }
    }

    // ---- scatter-add to dst ----
    #pragma unroll
    for (int e = 0; e < TILE_E; e++) {
        int valid = __shfl_sync(FULL, my_valid, e);
        int d     = __shfl_sync(FULL, my_dst,   e);
        if (!valid) continue;
        float* p = g_acc + (size_t)d * HID + 4*lane;
        atomicAdd(p + 0, acc2[e][0]);
        atomicAdd(p + 1, acc2[e][1]);
        atomicAdd(p + 2, acc2[e][2]);
        atomicAdd(p + 3, acc2[e][3]);
    }
}

__global__ __launch_bounds__(128)
void node_kernel(const float* __restrict__ Wo, const float* __restrict__ bo,
                 float* __restrict__ out, int n_nodes)
{
    __shared__ float smem[WARPS][TILE_E][HID];   // 16 KB
    const int warp = threadIdx.x >> 5;
    const int lane = threadIdx.x & 31;
    const int nbase = blockIdx.x * (WARPS * TILE_E) + warp * TILE_E;
    float (*x)[HID] = smem[warp];

    float my_inv = 1.0f;
    if (lane < TILE_E) {
        int n = nbase + lane;
        if (n < n_nodes) {
            float dg = g_deg[n];
            my_inv = 1.0f / fmaxf(dg, 1.0f);
        }
    }

    #pragma unroll
    for (int e = 0; e < TILE_E; e++) {
        float inv = __shfl_sync(FULL, my_inv, e);
        int n = nbase + e;
        float4 a = make_float4(0.f, 0.f, 0.f, 0.f);
        if (n < n_nodes) a = *(const float4*)(g_acc + (size_t)n * HID + 4*lane);
        a.x *= inv; a.y *= inv; a.z *= inv; a.w *= inv;
        *(float4*)(&x[e][4*lane]) = a;
    }
    __syncwarp();

    float acc[TILE_E][4];
    {
        float4 bb = *(const float4*)(bo + 4*lane);
        #pragma unroll
        for (int e = 0; e < TILE_E; e++) {
            acc[e][0] = bb.x; acc[e][1] = bb.y; acc[e][2] = bb.z; acc[e][3] = bb.w;
        }
    }
    #pragma unroll 4
    for (int k = 0; k < HID; k++) {
        float4 w = *(const float4*)(Wo + (size_t)k * HID + 4*lane);
        #pragma unroll
        for (int e = 0; e < TILE_E; e++) {
            float m = x[e][k];
            acc[e][0] = fmaf(m, w.x, acc[e][0]);
            acc[e][1] = fmaf(m, w.y, acc[e][1]);
            acc[e][2] = fmaf(m, w.z, acc[e][2]);
            acc[e][3] = fmaf(m, w.w, acc[e][3]);
        }
    }

    #pragma unroll
    for (int e = 0; e < TILE_E; e++) {
        int n = nbase + e;
        if (n < n_nodes) {
            float4 o = make_float4(acc[e][0], acc[e][1], acc[e][2], acc[e][3]);
            *(float4*)(out + (size_t)n * HID + 4*lane) = o;
        }
    }
}

extern "C" void kernel_launch(void* const* d_in, const int* in_sizes, int n_in,
                              void* d_out, int out_size) {
    const float* feat = (const float*)d_in[0];
    const float* pos  = (const float*)d_in[1];
    const int*   ei   = (const int*)d_in[2];
    const float* W1   = (const float*)d_in[3];
    const float* b1   = (const float*)d_in[4];
    const float* W2   = (const float*)d_in[5];
    const float* b2   = (const float*)d_in[6];
    const float* Wo   = (const float*)d_in[7];
    const float* bo   = (const float*)d_in[8];

    int n_nodes = in_sizes[0] / HID;
    int E = in_sizes[2] / 2;

    zero_kernel<<<256, 256>>>(n_nodes);

    int eblocks = (E + WARPS*TILE_E - 1) / (WARPS*TILE_E);
    edge_kernel<<<eblocks, 128>>>(feat, pos, ei, W1, b1, W2, b2, E);

    int nblocks = (n_nodes + WARPS*TILE_E - 1) / (WARPS*TILE_E);
    node_kernel<<<nblocks, 128>>>(Wo, bo, (float*)d_out, n_nodes);
}

// round 2
// speedup vs baseline: 1.0538x; 1.0538x over previous
#include <cuda_runtime.h>
#include <math.h>
#include <stdint.h>

#define HID 128
#define NB 32
#define KIN (2*HID + NB)   // 288
#define TILE_E 8           // edges per warp
#define WARPS 4
#define MAX_NODES 50000
#define FULL 0xffffffffu

// Scratch (allocation-free rule: static __device__ globals)
__device__ float g_acc[(size_t)MAX_NODES * HID];
__device__ float g_deg[MAX_NODES];
// Row-pair-interleaved weights: Wi[k/2][c][2] = { W[2k][c], W[2k+1][c] }
__device__ float g_W1i[KIN * HID];
__device__ float g_W2i[HID * HID];
__device__ float g_Woi[HID * HID];

// packed fp32x2 FMA: d = a*b + d (elementwise on the 2 packed floats)
__device__ __forceinline__ void ffma2(unsigned long long& d,
                                      unsigned long long a,
                                      unsigned long long b) {
    asm("fma.rn.f32x2 %0, %1, %2, %0;" : "+l"(d) : "l"(a), "l"(b));
}
__device__ __forceinline__ float hsum2(unsigned long long v) {
    float2 f = *reinterpret_cast<float2*>(&v);
    return f.x + f.y;
}

__global__ void zero_kernel(int n_nodes) {
    int tid = blockIdx.x * blockDim.x + threadIdx.x;
    int stride = gridDim.x * blockDim.x;
    int tot4 = (n_nodes * HID) / 4;
    float4 z = make_float4(0.f, 0.f, 0.f, 0.f);
    float4* p = (float4*)g_acc;
    for (int i = tid; i < tot4; i += stride) p[i] = z;
    for (int i = tid; i < n_nodes; i += stride) g_deg[i] = 0.0f;
}

// interleave W[K][H] (row-major) -> Wi[K/2][H][2]
__global__ void prep_kernel(const float* __restrict__ W1,
                            const float* __restrict__ W2,
                            const float* __restrict__ Wo) {
    int tid = blockIdx.x * blockDim.x + threadIdx.x;
    int stride = gridDim.x * blockDim.x;
    for (int i = tid; i < KIN * HID; i += stride) {
        int kp = i / (2 * HID);
        int r  = i % (2 * HID);
        int c  = r >> 1;
        int j  = r & 1;
        g_W1i[i] = W1[(size_t)(2 * kp + j) * HID + c];
    }
    for (int i = tid; i < HID * HID; i += stride) {
        int kp = i / (2 * HID);
        int r  = i % (2 * HID);
        int c  = r >> 1;
        int j  = r & 1;
        g_W2i[i] = W2[(size_t)(2 * kp + j) * HID + c];
        g_Woi[i] = Wo[(size_t)(2 * kp + j) * HID + c];
    }
}

__global__ __launch_bounds__(128)
void edge_kernel(const float* __restrict__ feat, const float* __restrict__ pos,
                 const int* __restrict__ ei,
                 const float* __restrict__ b1, const float* __restrict__ b2,
                 int E)
{
    __shared__ float smem[WARPS][TILE_E][KIN];   // 36864 B
    const int warp = threadIdx.x >> 5;
    const int lane = threadIdx.x & 31;
    const int ebase = blockIdx.x * (WARPS * TILE_E) + warp * TILE_E;
    float (*msg)[KIN] = smem[warp];

    // ---- per-edge metadata (lanes 0..7 own one edge each) ----
    int my_src = 0, my_dst = 0;
    float my_d = 0.0f;
    int my_valid = 0;
    if (lane < TILE_E) {
        int e = ebase + lane;
        if (e < E) {
            my_valid = 1;
            my_src = ei[e];
            my_dst = ei[E + e];
            float dx = pos[3*my_dst+0] - pos[3*my_src+0];
            float dy = pos[3*my_dst+1] - pos[3*my_src+1];
            float dz = pos[3*my_dst+2] - pos[3*my_src+2];
            float dist = sqrtf(dx*dx + dy*dy + dz*dz);
            my_d = fminf(dist, 5.0f);
            atomicAdd(&g_deg[my_dst], 1.0f);
        }
    }

    const float step   = 5.0f / (float)(NB - 1);
    const float inv_w  = 1.0f / (0.5f * (step + 0.01f));
    const float center = (float)lane * step;

    // ---- stage msg tile: [src feats | dst feats | rbf] ----
    #pragma unroll
    for (int e = 0; e < TILE_E; e++) {
        int s    = __shfl_sync(FULL, my_src, e);
        int d    = __shfl_sync(FULL, my_dst, e);
        float dd = __shfl_sync(FULL, my_d,   e);
        float4 fs = *(const float4*)(feat + (size_t)s * HID + 4*lane);
        float4 fd = *(const float4*)(feat + (size_t)d * HID + 4*lane);
        *(float4*)(&msg[e][4*lane])       = fs;
        *(float4*)(&msg[e][HID + 4*lane]) = fd;
        float t = (dd - center) * inv_w;
        msg[e][2*HID + lane] = __expf(-0.5f * t * t);
    }
    __syncwarp();

    // ---- layer 1: [8,288] @ [288,128]; lane owns 4 cols; k packed by 2 ----
    unsigned long long a1[TILE_E][4];
    #pragma unroll
    for (int e = 0; e < TILE_E; e++)
        #pragma unroll
        for (int c = 0; c < 4; c++) a1[e][c] = 0ull;

    {
        const ulonglong2* Wp = (const ulonglong2*)(g_W1i) + lane;  // lane's 4 cols: 2x ulonglong2 per kp
        #pragma unroll 2
        for (int kp = 0; kp < KIN/2; kp++) {
            ulonglong2 w01 = Wp[kp * (HID/2)];           // cols 4L,4L+1 (pairs over 2 k's)
            ulonglong2 w23 = Wp[kp * (HID/2) + (HID/4)]; // wait — see note below
            (void)w23;
            // correct addressing done below
            break;
        }
    }

    // Addressing note: g_W1i row kp has HID*2 floats = HID ulonglongs = HID/2 ulonglong2.
    // lane's 4 cols start at float offset kp*2*HID + 8*lane.
    {
        #pragma unroll 4
        for (int kp = 0; kp < KIN/2; kp++) {
            const float* wrow = g_W1i + (size_t)kp * (2*HID) + 8*lane;
            ulonglong2 wA = *(const ulonglong2*)(wrow);      // cols 4L, 4L+1
            ulonglong2 wB = *(const ulonglong2*)(wrow + 4);  // cols 4L+2, 4L+3
            #pragma unroll
            for (int e = 0; e < TILE_E; e++) {
                unsigned long long m2 = *(const unsigned long long*)(&msg[e][2*kp]);
                ffma2(a1[e][0], m2, wA.x);
                ffma2(a1[e][1], m2, wA.y);
                ffma2(a1[e][2], m2, wB.x);
                ffma2(a1[e][3], m2, wB.y);
            }
        }
    }
    __syncwarp();

    // ---- SiLU + bias, transpose back into smem (reuse first 128 cols) ----
    {
        float4 bb = *(const float4*)(b1 + 4*lane);
        #pragma unroll
        for (int e = 0; e < TILE_E; e++) {
            float v0 = hsum2(a1[e][0]) + bb.x;
            float v1 = hsum2(a1[e][1]) + bb.y;
            float v2 = hsum2(a1[e][2]) + bb.z;
            float v3 = hsum2(a1[e][3]) + bb.w;
            float4 s;
            s.x = v0 / (1.0f + __expf(-v0));
            s.y = v1 / (1.0f + __expf(-v1));
            s.z = v2 / (1.0f + __expf(-v2));
            s.w = v3 / (1.0f + __expf(-v3));
            *(float4*)(&msg[e][4*lane]) = s;
        }
    }
    __syncwarp();

    // ---- layer 2: [8,128] @ [128,128], k packed by 2 ----
    unsigned long long a2[TILE_E][4];
    #pragma unroll
    for (int e = 0; e < TILE_E; e++)
        #pragma unroll
        for (int c = 0; c < 4; c++) a2[e][c] = 0ull;

    {
        #pragma unroll 4
        for (int kp = 0; kp < HID/2; kp++) {
            const float* wrow = g_W2i + (size_t)kp * (2*HID) + 8*lane;
            ulonglong2 wA = *(const ulonglong2*)(wrow);
            ulonglong2 wB = *(const ulonglong2*)(wrow + 4);
            #pragma unroll
            for (int e = 0; e < TILE_E; e++) {
                unsigned long long m2 = *(const unsigned long long*)(&msg[e][2*kp]);
                ffma2(a2[e][0], m2, wA.x);
                ffma2(a2[e][1], m2, wA.y);
                ffma2(a2[e][2], m2, wB.x);
                ffma2(a2[e][3], m2, wB.y);
            }
        }
    }

    // ---- bias + scatter-add to dst ----
    float4 bb2 = *(const float4*)(b2 + 4*lane);
    #pragma unroll
    for (int e = 0; e < TILE_E; e++) {
        int valid = __shfl_sync(FULL, my_valid, e);
        int d     = __shfl_sync(FULL, my_dst,   e);
        if (!valid) continue;
        float* p = g_acc + (size_t)d * HID + 4*lane;
        atomicAdd(p + 0, hsum2(a2[e][0]) + bb2.x);
        atomicAdd(p + 1, hsum2(a2[e][1]) + bb2.y);
        atomicAdd(p + 2, hsum2(a2[e][2]) + bb2.z);
        atomicAdd(p + 3, hsum2(a2[e][3]) + bb2.w);
    }
}

__global__ __launch_bounds__(128)
void node_kernel(const float* __restrict__ bo,
                 float* __restrict__ out, int n_nodes)
{
    __shared__ float smem[WARPS][TILE_E][HID];   // 16 KB
    const int warp = threadIdx.x >> 5;
    const int lane = threadIdx.x & 31;
    const int nbase = blockIdx.x * (WARPS * TILE_E) + warp * TILE_E;
    float (*x)[HID] = smem[warp];

    float my_inv = 1.0f;
    if (lane < TILE_E) {
        int n = nbase + lane;
        if (n < n_nodes) {
            float dg = g_deg[n];
            my_inv = 1.0f / fmaxf(dg, 1.0f);
        }
    }

    #pragma unroll
    for (int e = 0; e < TILE_E; e++) {
        float inv = __shfl_sync(FULL, my_inv, e);
        int n = nbase + e;
        float4 a = make_float4(0.f, 0.f, 0.f, 0.f);
        if (n < n_nodes) a = *(const float4*)(g_acc + (size_t)n * HID + 4*lane);
        a.x *= inv; a.y *= inv; a.z *= inv; a.w *= inv;
        *(float4*)(&x[e][4*lane]) = a;
    }
    __syncwarp();

    unsigned long long acc[TILE_E][4];
    #pragma unroll
    for (int e = 0; e < TILE_E; e++)
        #pragma unroll
        for (int c = 0; c < 4; c++) acc[e][c] = 0ull;

    #pragma unroll 4
    for (int kp = 0; kp < HID/2; kp++) {
        const float* wrow = g_Woi + (size_t)kp * (2*HID) + 8*lane;
        ulonglong2 wA = *(const ulonglong2*)(wrow);
        ulonglong2 wB = *(const ulonglong2*)(wrow + 4);
        #pragma unroll
        for (int e = 0; e < TILE_E; e++) {
            unsigned long long m2 = *(const unsigned long long*)(&x[e][2*kp]);
            ffma2(acc[e][0], m2, wA.x);
            ffma2(acc[e][1], m2, wA.y);
            ffma2(acc[e][2], m2, wB.x);
            ffma2(acc[e][3], m2, wB.y);
        }
    }

    float4 bb = *(const float4*)(bo + 4*lane);
    #pragma unroll
    for (int e = 0; e < TILE_E; e++) {
        int n = nbase + e;
        if (n < n_nodes) {
            float4 o;
            o.x = hsum2(acc[e][0]) + bb.x;
            o.y = hsum2(acc[e][1]) + bb.y;
            o.z = hsum2(acc[e][2]) + bb.z;
            o.w = hsum2(acc[e][3]) + bb.w;
            *(float4*)(out + (size_t)n * HID + 4*lane) = o;
        }
    }
}

extern "C" void kernel_launch(void* const* d_in, const int* in_sizes, int n_in,
                              void* d_out, int out_size) {
    const float* feat = (const float*)d_in[0];
    const float* pos  = (const float*)d_in[1];
    const int*   ei   = (const int*)d_in[2];
    const float* W1   = (const float*)d_in[3];
    const float* b1   = (const float*)d_in[4];
    const float* W2   = (const float*)d_in[5];
    const float* b2   = (const float*)d_in[6];
    const float* Wo   = (const float*)d_in[7];
    const float* bo   = (const float*)d_in[8];

    int n_nodes = in_sizes[0] / HID;
    int E = in_sizes[2] / 2;

    zero_kernel<<<512, 256>>>(n_nodes);
    prep_kernel<<<128, 256>>>(W1, W2, Wo);

    int eblocks = (E + WARPS*TILE_E - 1) / (WARPS*TILE_E);
    edge_kernel<<<eblocks, 128>>>(feat, pos, ei, b1, b2, E);

    int nblocks = (n_nodes + WARPS*TILE_E - 1) / (WARPS*TILE_E);
    node_kernel<<<nblocks, 128>>>(bo, (float*)d_out, n_nodes);
}

// round 6
// speedup vs baseline: 2.1949x; 2.0828x over previous
#include <cuda_runtime.h>
#include <math.h>
#include <stdint.h>

#define HID 128
#define NB 32
#define TILE_M 128
#define MAX_NODES 50000
#define FULL 0xffffffffu

// padded strides (floats)
#define W_STRIDE 264      // per (kstep,tig) row of 256 interleaved weights
#define A_STRIDE 40       // per edge row of 32 permuted k values

// dynamic smem layout (byte offsets)
#define OFF_W1   0            // 144 rows * 264 * 4 = 152064
#define OFF_W2C  152064       // 16 rows  * 264 * 4 = 16896
#define OFF_A    168960       // 128 * 40 * 4      = 20480
#define OFF_SRC  189440       // 512
#define OFF_DST  189952       // 512
#define OFF_DIST 190464       // 512
#define OFF_B1   190976       // 512
#define OFF_B2   191488       // 512
#define SMEM_DYN 192000

// ---------------- device scratch ----------------
__device__ float g_acc[(size_t)MAX_NODES * HID];
__device__ float g_deg[MAX_NODES];
__device__ float g_W1p[144 * 256];   // [ks*4+tig][n*2+j], value = tf32(W1[ks*8+tig+4j][n])
__device__ float g_W2p[64 * 256];    // same for W2 (16 ksteps)
__device__ float g_Woi[HID * HID];   // pair-interleaved for node kernel

__device__ __forceinline__ float tf32r(float v) {
    uint32_t u; asm("cvt.rna.tf32.f32 %0, %1;" : "=r"(u) : "f"(v));
    return __uint_as_float(u);
}

#define MMA_TF32(C, a0, a1, a2, a3, b0, b1) \
    asm volatile("mma.sync.aligned.m16n8k8.row.col.f32.tf32.tf32.f32 " \
        "{%0,%1,%2,%3}, {%4,%5,%6,%7}, {%8,%9}, {%0,%1,%2,%3};" \
        : "+f"((C)[0]), "+f"((C)[1]), "+f"((C)[2]), "+f"((C)[3]) \
        : "r"(a0), "r"(a1), "r"(a2), "r"(a3), "r"(b0), "r"(b1))

__device__ __forceinline__ void red_add_v4(float* addr, float a, float b, float c, float d) {
    asm volatile("red.global.add.v4.f32 [%0], {%1,%2,%3,%4};"
                 :: "l"(addr), "f"(a), "f"(b), "f"(c), "f"(d) : "memory");
}

// ---------------- small kernels ----------------
__global__ void zero_kernel(int n_nodes) {
    int tid = blockIdx.x * blockDim.x + threadIdx.x;
    int stride = gridDim.x * blockDim.x;
    int tot4 = (n_nodes * HID) / 4;
    float4 z = make_float4(0.f, 0.f, 0.f, 0.f);
    float4* p = (float4*)g_acc;
    for (int i = tid; i < tot4; i += stride) p[i] = z;
    for (int i = tid; i < n_nodes; i += stride) g_deg[i] = 0.0f;
}

__global__ void prep_kernel(const float* __restrict__ W1, const float* __restrict__ W2,
                            const float* __restrict__ Wo) {
    int tid = blockIdx.x * blockDim.x + threadIdx.x;
    int stride = gridDim.x * blockDim.x;
    for (int i = tid; i < 144 * 256; i += stride) {
        int row = i >> 8, c = i & 255;
        int ks = row >> 2, tg = row & 3;
        int n = c >> 1, j = c & 1;
        int k = ks * 8 + tg + 4 * j;
        g_W1p[i] = tf32r(W1[(size_t)k * HID + n]);
    }
    for (int i = tid; i < 64 * 256; i += stride) {
        int row = i >> 8, c = i & 255;
        int ks = row >> 2, tg = row & 3;
        int n = c >> 1, j = c & 1;
        int k = ks * 8 + tg + 4 * j;
        g_W2p[i] = tf32r(W2[(size_t)k * HID + n]);
    }
    for (int i = tid; i < HID * HID; i += stride) {
        int kp = i / (2 * HID);
        int r = i % (2 * HID);
        int cc = r >> 1, j = r & 1;
        g_Woi[i] = Wo[(size_t)(2 * kp + j) * HID + cc];
    }
}

// ---------------- edge kernel: persistent, mma.sync tf32 ----------------
__global__ __launch_bounds__(256, 1)
void edge_kernel(const float* __restrict__ feat, const float* __restrict__ pos,
                 const int* __restrict__ ei, const float* __restrict__ b1,
                 const float* __restrict__ b2, int E)
{
    extern __shared__ float sm[];
    float* smW1 = sm;                       // [144][264]
    float* smW2 = sm + OFF_W2C / 4;         // [16][264]
    float* smA  = sm + OFF_A / 4;           // [128][40]
    int*   sSrc = (int*)(sm + OFF_SRC / 4);
    int*   sDst = (int*)(sm + OFF_DST / 4);
    float* sDist = sm + OFF_DIST / 4;
    float* sB1  = sm + OFF_B1 / 4;
    float* sB2  = sm + OFF_B2 / 4;

    const int tid = threadIdx.x;
    const int wid = tid >> 5, lane = tid & 31;
    const int mg = wid >> 1, nh = wid & 1;
    const int gid = lane >> 2, tig = lane & 3;
    const int m = tid >> 1, h = tid & 1;     // staging role: edge row m, k-half h

    // W1 resident (interleaved layout, pad gap unwritten)
    for (int i = tid; i < 144 * 64; i += 256) {
        int row = i >> 6, c4 = i & 63;
        ((float4*)(smW1 + row * W_STRIDE))[c4] = ((const float4*)g_W1p)[i];
    }
    if (tid < HID) { sB1[tid] = b1[tid]; sB2[tid] = b2[tid]; }

    const int ntiles = (E + TILE_M - 1) / TILE_M;
    const float step = 5.0f / (float)(NB - 1);
    const float invw = 1.0f / (0.5f * (step + 0.01f));

    for (int t = blockIdx.x; t < ntiles; t += gridDim.x) {
        const int ebase = t * TILE_M;
        __syncthreads();   // protect meta/smA against previous tile readers

        if (tid < TILE_M) {
            int e = ebase + tid;
            int s = 0, d = 0; float dist = 0.0f;
            if (e < E) {
                s = ei[e]; d = ei[E + e];
                float dx = pos[3*d+0] - pos[3*s+0];
                float dy = pos[3*d+1] - pos[3*s+1];
                float dz = pos[3*d+2] - pos[3*s+2];
                dist = fminf(sqrtf(dx*dx + dy*dy + dz*dz), 5.0f);
                atomicAdd(&g_deg[d], 1.0f);
            }
            sSrc[tid] = s; sDst[tid] = d; sDist[tid] = dist;
        }
        __syncthreads();

        float c1f[2][8][4];
        #pragma unroll
        for (int a = 0; a < 2; a++)
            #pragma unroll
            for (int b = 0; b < 8; b++)
                #pragma unroll
                for (int c = 0; c < 4; c++) c1f[a][b][c] = 0.0f;

        // prefetch chunk 0 (src feats cols 0..31)
        float vv[16];
        {
            int node = sSrc[m];
            const float4* p = (const float4*)(feat + (size_t)node * HID + h * 16);
            float4 x0 = __ldg(p), x1 = __ldg(p+1), x2 = __ldg(p+2), x3 = __ldg(p+3);
            vv[0]=x0.x; vv[1]=x0.y; vv[2]=x0.z; vv[3]=x0.w;
            vv[4]=x1.x; vv[5]=x1.y; vv[6]=x1.z; vv[7]=x1.w;
            vv[8]=x2.x; vv[9]=x2.y; vv[10]=x2.z; vv[11]=x2.w;
            vv[12]=x3.x; vv[13]=x3.y; vv[14]=x3.z; vv[15]=x3.w;
        }

        // ---------- layer 1: 9 chunks of k=32 ----------
        #pragma unroll
        for (int c = 0; c < 9; c++) {
            // store prefetched values into permuted A buffer (tf32-rounded)
            #pragma unroll
            for (int q = 0; q < 2; q++)
                #pragma unroll
                for (int t2 = 0; t2 < 4; t2++) {
                    float2 pr = make_float2(tf32r(vv[q*8 + t2]), tf32r(vv[q*8 + t2 + 4]));
                    *(float2*)(smA + m * A_STRIDE + (2*h + q) * 8 + 2*t2) = pr;
                }
            __syncthreads();

            // prefetch next chunk while mma runs
            float vn[16];
            if (c < 8) {
                if (c < 7) {
                    int node = ((c + 1) < 4) ? sSrc[m] : sDst[m];
                    const float4* p = (const float4*)(feat + (size_t)node * HID + ((c+1) & 3) * 32 + h * 16);
                    float4 x0 = __ldg(p), x1 = __ldg(p+1), x2 = __ldg(p+2), x3 = __ldg(p+3);
                    vn[0]=x0.x; vn[1]=x0.y; vn[2]=x0.z; vn[3]=x0.w;
                    vn[4]=x1.x; vn[5]=x1.y; vn[6]=x1.z; vn[7]=x1.w;
                    vn[8]=x2.x; vn[9]=x2.y; vn[10]=x2.z; vn[11]=x2.w;
                    vn[12]=x3.x; vn[13]=x3.y; vn[14]=x3.z; vn[15]=x3.w;
                } else {
                    float dist = sDist[m];
                    #pragma unroll
                    for (int i = 0; i < 16; i++) {
                        float tt = (dist - (float)(h*16 + i) * step) * invw;
                        vn[i] = __expf(-0.5f * tt * tt);
                    }
                }
            }

            #pragma unroll
            for (int s = 0; s < 4; s++) {
                const float* ap0 = smA + (mg*32 + gid) * A_STRIDE + s*8 + 2*tig;
                uint2 aL0 = *(const uint2*)ap0;
                uint2 aH0 = *(const uint2*)(ap0 + 8 * A_STRIDE);
                const float* ap1 = ap0 + 16 * A_STRIDE;
                uint2 aL1 = *(const uint2*)ap1;
                uint2 aH1 = *(const uint2*)(ap1 + 8 * A_STRIDE);
                const float* wrow = smW1 + (c*16 + s*4 + tig) * W_STRIDE;
                #pragma unroll
                for (int nt = 0; nt < 8; nt++) {
                    uint2 b = *(const uint2*)(wrow + (nh*64 + nt*8 + gid) * 2);
                    MMA_TF32(c1f[0][nt], aL0.x, aH0.x, aL0.y, aH0.y, b.x, b.y);
                    MMA_TF32(c1f[1][nt], aL1.x, aH1.x, aL1.y, aH1.y, b.x, b.y);
                }
            }
            __syncthreads();
            if (c < 8) {
                #pragma unroll
                for (int i = 0; i < 16; i++) vv[i] = vn[i];
            }
        }

        // ---------- layer 2: 4 chunks of k=32 ----------
        float c2f[2][8][4];
        #pragma unroll
        for (int a = 0; a < 2; a++)
            #pragma unroll
            for (int b = 0; b < 8; b++)
                #pragma unroll
                for (int c = 0; c < 4; c++) c2f[a][b][c] = 0.0f;

        #pragma unroll
        for (int c2 = 0; c2 < 4; c2++) {
            // stream W2 chunk (16 rows of 256) into smW2
            for (int i = tid; i < 16 * 64; i += 256) {
                int row = i >> 6, c4 = i & 63;
                ((float4*)(smW2 + row * W_STRIDE))[c4] =
                    ((const float4*)(g_W2p + c2 * 4096))[i];
            }
            // silu staging: warps owning cols [32*c2, 32*c2+32)
            if (nh == (c2 >> 1)) {
                #pragma unroll
                for (int mt = 0; mt < 2; mt++) {
                    int r0 = mg*32 + mt*16 + gid;
                    #pragma unroll
                    for (int s = 0; s < 4; s++) {
                        int nt = 4 * (c2 & 1) + s;
                        const float* C = c1f[mt][nt];
                        int col0 = nh*64 + nt*8 + 2*tig;
                        float b1a = sB1[col0], b1b = sB1[col0 + 1];
                        float v0 = C[0] + b1a, v1 = C[1] + b1b;
                        float v2 = C[2] + b1a, v3 = C[3] + b1b;
                        v0 = __fdividef(v0, 1.0f + __expf(-v0));
                        v1 = __fdividef(v1, 1.0f + __expf(-v1));
                        v2 = __fdividef(v2, 1.0f + __expf(-v2));
                        v3 = __fdividef(v3, 1.0f + __expf(-v3));
                        int w0 = 2*tig, w1 = 2*tig + 1;
                        int p0 = 2*(w0 & 3) + (w0 >> 2);
                        int p1 = 2*(w1 & 3) + (w1 >> 2);
                        float* base0 = smA + r0 * A_STRIDE + s*8;
                        base0[p0] = tf32r(v0); base0[p1] = tf32r(v1);
                        float* base1 = smA + (r0 + 8) * A_STRIDE + s*8;
                        base1[p0] = tf32r(v2); base1[p1] = tf32r(v3);
                    }
                }
            }
            __syncthreads();

            #pragma unroll
            for (int s = 0; s < 4; s++) {
                const float* ap0 = smA + (mg*32 + gid) * A_STRIDE + s*8 + 2*tig;
                uint2 aL0 = *(const uint2*)ap0;
                uint2 aH0 = *(const uint2*)(ap0 + 8 * A_STRIDE);
                const float* ap1 = ap0 + 16 * A_STRIDE;
                uint2 aL1 = *(const uint2*)ap1;
                uint2 aH1 = *(const uint2*)(ap1 + 8 * A_STRIDE);
                const float* wrow = smW2 + (s*4 + tig) * W_STRIDE;
                #pragma unroll
                for (int nt = 0; nt < 8; nt++) {
                    uint2 b = *(const uint2*)(wrow + (nh*64 + nt*8 + gid) * 2);
                    MMA_TF32(c2f[0][nt], aL0.x, aH0.x, aL0.y, aH0.y, b.x, b.y);
                    MMA_TF32(c2f[1][nt], aL1.x, aH1.x, aL1.y, aH1.y, b.x, b.y);
                }
            }
            __syncthreads();
        }

        // ---------- epilogue: +b2, pair lanes, vector red scatter ----------
        #pragma unroll
        for (int mt = 0; mt < 2; mt++) {
            int r0 = mg*32 + mt*16 + gid;
            int r1 = r0 + 8;
            int d0 = sDst[r0], d1 = sDst[r1];
            bool ok0 = (ebase + r0) < E, ok1 = (ebase + r1) < E;
            #pragma unroll
            for (int nt = 0; nt < 8; nt++) {
                float* C = c2f[mt][nt];
                float q0 = __shfl_xor_sync(FULL, C[0], 1);
                float q1 = __shfl_xor_sync(FULL, C[1], 1);
                float q2 = __shfl_xor_sync(FULL, C[2], 1);
                float q3 = __shfl_xor_sync(FULL, C[3], 1);
                if ((tig & 1) == 0) {
                    int cb = nh*64 + nt*8 + 2*tig;
                    float4 bb = *(const float4*)(sB2 + cb);
                    if (ok0)
                        red_add_v4(g_acc + (size_t)d0 * HID + cb,
                                   C[0] + bb.x, C[1] + bb.y, q0 + bb.z, q1 + bb.w);
                } else {
                    int cb = nh*64 + nt*8 + 2*(tig - 1);
                    float4 bb = *(const float4*)(sB2 + cb);
                    if (ok1)
                        red_add_v4(g_acc + (size_t)d1 * HID + cb,
                                   q2 + bb.x, q3 + bb.y, C[2] + bb.z, C[3] + bb.w);
                }
            }
        }
    }
}

// ---------------- node output GEMM (validated, fp32) ----------------
__device__ __forceinline__ void ffma2(unsigned long long& d, unsigned long long a, unsigned long long b) {
    asm("fma.rn.f32x2 %0, %1, %2, %0;" : "+l"(d) : "l"(a), "l"(b));
}
__device__ __forceinline__ float hsum2(unsigned long long v) {
    float2 f = *reinterpret_cast<float2*>(&v);
    return f.x + f.y;
}

__global__ __launch_bounds__(128)
void node_kernel(const float* __restrict__ bo, float* __restrict__ out, int n_nodes)
{
    __shared__ float smem[4][8][HID];
    const int warp = threadIdx.x >> 5;
    const int lane = threadIdx.x & 31;
    const int nbase = blockIdx.x * 32 + warp * 8;
    float (*x)[HID] = smem[warp];

    float my_inv = 1.0f;
    if (lane < 8) {
        int n = nbase + lane;
        if (n < n_nodes) my_inv = 1.0f / fmaxf(g_deg[n], 1.0f);
    }
    #pragma unroll
    for (int e = 0; e < 8; e++) {
        float inv = __shfl_sync(FULL, my_inv, e);
        int n = nbase + e;
        float4 a = make_float4(0.f, 0.f, 0.f, 0.f);
        if (n < n_nodes) a = *(const float4*)(g_acc + (size_t)n * HID + 4 * lane);
        a.x *= inv; a.y *= inv; a.z *= inv; a.w *= inv;
        *(float4*)(&x[e][4 * lane]) = a;
    }
    __syncwarp();

    unsigned long long acc[8][4];
    #pragma unroll
    for (int e = 0; e < 8; e++)
        #pragma unroll
        for (int c = 0; c < 4; c++) acc[e][c] = 0ull;

    #pragma unroll 4
    for (int kp = 0; kp < HID / 2; kp++) {
        const float* wrow = g_Woi + (size_t)kp * (2 * HID) + 8 * lane;
        ulonglong2 wA = *(const ulonglong2*)(wrow);
        ulonglong2 wB = *(const ulonglong2*)(wrow + 4);
        #pragma unroll
        for (int e = 0; e < 8; e++) {
            unsigned long long m2 = *(const unsigned long long*)(&x[e][2 * kp]);
            ffma2(acc[e][0], m2, wA.x);
            ffma2(acc[e][1], m2, wA.y);
            ffma2(acc[e][2], m2, wB.x);
            ffma2(acc[e][3], m2, wB.y);
        }
    }
    float4 bb = *(const float4*)(bo + 4 * lane);
    #pragma unroll
    for (int e = 0; e < 8; e++) {
        int n = nbase + e;
        if (n < n_nodes) {
            float4 o;
            o.x = hsum2(acc[e][0]) + bb.x;
            o.y = hsum2(acc[e][1]) + bb.y;
            o.z = hsum2(acc[e][2]) + bb.z;
            o.w = hsum2(acc[e][3]) + bb.w;
            *(float4*)(out + (size_t)n * HID + 4 * lane) = o;
        }
    }
}

// ---------------- launch ----------------
extern "C" void kernel_launch(void* const* d_in, const int* in_sizes, int n_in,
                              void* d_out, int out_size) {
    const float* feat = (const float*)d_in[0];
    const float* pos  = (const float*)d_in[1];
    const int*   ei   = (const int*)d_in[2];
    const float* W1   = (const float*)d_in[3];
    const float* b1   = (const float*)d_in[4];
    const float* W2   = (const float*)d_in[5];
    const float* b2   = (const float*)d_in[6];
    const float* Wo   = (const float*)d_in[7];
    const float* bo   = (const float*)d_in[8];

    int n_nodes = in_sizes[0] / HID;
    int E = in_sizes[2] / 2;

    (void)cudaFuncSetAttribute(edge_kernel, cudaFuncAttributeMaxDynamicSharedMemorySize, SMEM_DYN);

    zero_kernel<<<512, 256>>>(n_nodes);
    prep_kernel<<<64, 256>>>(W1, W2, Wo);
    edge_kernel<<<148, 256, SMEM_DYN>>>(feat, pos, ei, b1, b2, E);

    int nblocks = (n_nodes + 31) / 32;
    node_kernel<<<nblocks, 128>>>(bo, (float*)d_out, n_nodes);
}

// round 7
// speedup vs baseline: 3.3351x; 1.5195x over previous
#include <cuda_runtime.h>
#include <cuda_fp16.h>
#include <math.h>
#include <stdint.h>

#define HID 128
#define NB 32
#define TILE_M 128
#define MAX_NODES 50000
#define FULL 0xffffffffu

// strides in halves
#define WSTR 520          // weight row: 128 n * 4 halves + 8 pad
#define A1STR 40          // A1 row: 32 halves + 8 pad
#define A2STR 136         // A2 row: 128 halves + 8 pad
#define A1BUF (TILE_M * A1STR)

// dynamic smem layout (byte offsets)
#define OFF_W1   0            // 72 * 520 * 2  = 74880
#define OFF_W2   74880        // 32 * 520 * 2  = 33280
#define OFF_A1   108160       // 2 * 128*40*2  = 20480
#define OFF_A2   128640       // 128 * 136 * 2 = 34816
#define OFF_SRC  163456       // 512
#define OFF_DST  163968       // 512
#define OFF_DIST 164480       // 512
#define OFF_B1   164992       // 512
#define OFF_B2   165504       // 512
#define SMEM_DYN 166016

// ---------------- device scratch ----------------
__device__ float  g_acc[(size_t)MAX_NODES * HID];
__device__ float  g_deg[MAX_NODES];
__device__ __half g_W1h[72 * 512];   // [ (ks16*4+tig) ][ n*4 + j ], k = ks16*16 + 2*tig + (j&1) + 8*(j>>1)
__device__ __half g_W2h[32 * 512];
__device__ float  g_Woi[HID * HID];  // pair-interleaved for node kernel

#define MMA_F16(C, a0, a1, a2, a3, b0, b1) \
    asm volatile("mma.sync.aligned.m16n8k16.row.col.f32.f16.f16.f32 " \
        "{%0,%1,%2,%3}, {%4,%5,%6,%7}, {%8,%9}, {%0,%1,%2,%3};" \
        : "+f"((C)[0]), "+f"((C)[1]), "+f"((C)[2]), "+f"((C)[3]) \
        : "r"(a0), "r"(a1), "r"(a2), "r"(a3), "r"(b0), "r"(b1))

__device__ __forceinline__ void red_add_v4(float* addr, float a, float b, float c, float d) {
    asm volatile("red.global.add.v4.f32 [%0], {%1,%2,%3,%4};"
                 :: "l"(addr), "f"(a), "f"(b), "f"(c), "f"(d) : "memory");
}
__device__ __forceinline__ uint32_t h2u(__half2 h) { return *reinterpret_cast<uint32_t*>(&h); }

// ---------------- small kernels ----------------
__global__ void zero_kernel(int n_nodes) {
    int tid = blockIdx.x * blockDim.x + threadIdx.x;
    int stride = gridDim.x * blockDim.x;
    int tot4 = (n_nodes * HID) / 4;
    float4 z = make_float4(0.f, 0.f, 0.f, 0.f);
    float4* p = (float4*)g_acc;
    for (int i = tid; i < tot4; i += stride) p[i] = z;
    for (int i = tid; i < n_nodes; i += stride) g_deg[i] = 0.0f;
}

__global__ void prep_kernel(const float* __restrict__ W1, const float* __restrict__ W2,
                            const float* __restrict__ Wo) {
    int tid = blockIdx.x * blockDim.x + threadIdx.x;
    int stride = gridDim.x * blockDim.x;
    for (int i = tid; i < 72 * 512; i += stride) {
        int row = i >> 9, r = i & 511;
        int n = r >> 2, j = r & 3;
        int k = (row >> 2) * 16 + 2 * (row & 3) + (j & 1) + 8 * (j >> 1);
        g_W1h[i] = __float2half(W1[(size_t)k * HID + n]);
    }
    for (int i = tid; i < 32 * 512; i += stride) {
        int row = i >> 9, r = i & 511;
        int n = r >> 2, j = r & 3;
        int k = (row >> 2) * 16 + 2 * (row & 3) + (j & 1) + 8 * (j >> 1);
        g_W2h[i] = __float2half(W2[(size_t)k * HID + n]);
    }
    for (int i = tid; i < HID * HID; i += stride) {
        int kp = i / (2 * HID);
        int r = i % (2 * HID);
        int cc = r >> 1, j = r & 1;
        g_Woi[i] = Wo[(size_t)(2 * kp + j) * HID + cc];
    }
}

// ---------------- edge kernel: persistent, mma.sync fp16 ----------------
__global__ __launch_bounds__(256, 1)
void edge_kernel(const float* __restrict__ feat, const float* __restrict__ pos,
                 const int* __restrict__ ei, const float* __restrict__ b1,
                 const float* __restrict__ b2, int E)
{
    extern __shared__ char smc[];
    __half* smW1 = (__half*)(smc + OFF_W1);     // [72][520]
    __half* smW2 = (__half*)(smc + OFF_W2);     // [32][520]
    __half* smA1 = (__half*)(smc + OFF_A1);     // 2 x [128][40]
    __half* smA2 = (__half*)(smc + OFF_A2);     // [128][136]
    int*    sSrc = (int*)(smc + OFF_SRC);
    int*    sDst = (int*)(smc + OFF_DST);
    float*  sDist = (float*)(smc + OFF_DIST);
    float*  sB1  = (float*)(smc + OFF_B1);
    float*  sB2  = (float*)(smc + OFF_B2);

    const int tid = threadIdx.x;
    const int wid = tid >> 5, lane = tid & 31;
    const int mg = wid >> 1, nh = wid & 1;       // warp tile: rows mg*32..+31, cols nh*64..+63
    const int gid = lane >> 2, tig = lane & 3;
    const int m = tid >> 1, h = tid & 1;         // staging role: edge row m, k-half h

    // resident weights (compact global -> padded smem rows)
    for (int i = tid; i < 72 * 64; i += 256) {
        int row = i >> 6, q = i & 63;
        *((uint4*)(smW1 + row * WSTR) + q) = ((const uint4*)g_W1h)[i];
    }
    for (int i = tid; i < 32 * 64; i += 256) {
        int row = i >> 6, q = i & 63;
        *((uint4*)(smW2 + row * WSTR) + q) = ((const uint4*)g_W2h)[i];
    }
    if (tid < HID) { sB1[tid] = b1[tid]; sB2[tid] = b2[tid]; }

    const int ntiles = (E + TILE_M - 1) / TILE_M;
    const float step = 5.0f / (float)(NB - 1);
    const float invw = 1.0f / (0.5f * (step + 0.01f));

    for (int t = blockIdx.x; t < ntiles; t += gridDim.x) {
        const int ebase = t * TILE_M;
        __syncthreads();   // protect meta + A2 against previous-tile readers

        if (tid < TILE_M) {
            int e = ebase + tid;
            int s = 0, d = 0; float dist = 0.0f;
            if (e < E) {
                s = ei[e]; d = ei[E + e];
                float dx = pos[3*d+0] - pos[3*s+0];
                float dy = pos[3*d+1] - pos[3*s+1];
                float dz = pos[3*d+2] - pos[3*s+2];
                dist = fminf(sqrtf(dx*dx + dy*dy + dz*dz), 5.0f);
                atomicAdd(&g_deg[d], 1.0f);
            }
            sSrc[tid] = s; sDst[tid] = d; sDist[tid] = dist;
        }
        __syncthreads();

        float c1f[2][8][4];
        #pragma unroll
        for (int a = 0; a < 2; a++)
            #pragma unroll
            for (int b = 0; b < 8; b++)
                #pragma unroll
                for (int c = 0; c < 4; c++) c1f[a][b][c] = 0.0f;

        // prefetch chunk 0 (src feats, cols h*16..h*16+15)
        float vv[16];
        {
            int node = sSrc[m];
            const float4* p = (const float4*)(feat + (size_t)node * HID + h * 16);
            float4 x0 = __ldg(p), x1 = __ldg(p+1), x2 = __ldg(p+2), x3 = __ldg(p+3);
            vv[0]=x0.x; vv[1]=x0.y; vv[2]=x0.z; vv[3]=x0.w;
            vv[4]=x1.x; vv[5]=x1.y; vv[6]=x1.z; vv[7]=x1.w;
            vv[8]=x2.x; vv[9]=x2.y; vv[10]=x2.z; vv[11]=x2.w;
            vv[12]=x3.x; vv[13]=x3.y; vv[14]=x3.z; vv[15]=x3.w;
        }

        // ---------- layer 1: 9 chunks of k=32, double-buffered, 1 sync/chunk ----------
        #pragma unroll
        for (int c = 0; c < 9; c++) {
            {   // stage vv (chunk c) into buffer c&1, permuted fp16 layout
                __half* arow = smA1 + (c & 1) * A1BUF + m * A1STR + h * 16;
                #pragma unroll
                for (int t2 = 0; t2 < 4; t2++) {
                    uint2 u;
                    u.x = h2u(__floats2half2_rn(vv[2*t2],     vv[2*t2 + 1]));
                    u.y = h2u(__floats2half2_rn(vv[2*t2 + 8], vv[2*t2 + 9]));
                    *(uint2*)(arow + t2 * 4) = u;
                }
            }
            __syncthreads();

            // prefetch next chunk during mma
            float vn[16];
            if (c < 8) {
                if (c < 7) {
                    int node = ((c + 1) < 4) ? sSrc[m] : sDst[m];
                    const float4* p = (const float4*)(feat + (size_t)node * HID + ((c+1) & 3) * 32 + h * 16);
                    float4 x0 = __ldg(p), x1 = __ldg(p+1), x2 = __ldg(p+2), x3 = __ldg(p+3);
                    vn[0]=x0.x; vn[1]=x0.y; vn[2]=x0.z; vn[3]=x0.w;
                    vn[4]=x1.x; vn[5]=x1.y; vn[6]=x1.z; vn[7]=x1.w;
                    vn[8]=x2.x; vn[9]=x2.y; vn[10]=x2.z; vn[11]=x2.w;
                    vn[12]=x3.x; vn[13]=x3.y; vn[14]=x3.z; vn[15]=x3.w;
                } else {
                    float dist = sDist[m];
                    #pragma unroll
                    for (int i = 0; i < 16; i++) {
                        float tt = (dist - (float)(h*16 + i) * step) * invw;
                        vn[i] = __expf(-0.5f * tt * tt);
                    }
                }
            }

            const __half* Ab = smA1 + (c & 1) * A1BUF;
            #pragma unroll
            for (int s = 0; s < 2; s++) {
                uint2 a0 = *(const uint2*)(Ab + (mg*32 + gid     ) * A1STR + s*16 + tig*4);
                uint2 a1 = *(const uint2*)(Ab + (mg*32 + gid +  8) * A1STR + s*16 + tig*4);
                uint2 a2 = *(const uint2*)(Ab + (mg*32 + gid + 16) * A1STR + s*16 + tig*4);
                uint2 a3 = *(const uint2*)(Ab + (mg*32 + gid + 24) * A1STR + s*16 + tig*4);
                const __half* wrow = smW1 + ((c*2 + s)*4 + tig) * WSTR;
                #pragma unroll
                for (int nt = 0; nt < 8; nt++) {
                    uint2 b = *(const uint2*)(wrow + (nh*64 + nt*8 + gid) * 4);
                    MMA_F16(c1f[0][nt], a0.x, a1.x, a0.y, a1.y, b.x, b.y);
                    MMA_F16(c1f[1][nt], a2.x, a3.x, a2.y, a3.y, b.x, b.y);
                }
            }
            if (c < 8) {
                #pragma unroll
                for (int i = 0; i < 16; i++) vv[i] = vn[i];
            }
        }

        // ---------- SiLU -> stage full A2 [128][128] fp16 ----------
        #pragma unroll
        for (int mt = 0; mt < 2; mt++) {
            int row0 = mg*32 + mt*16 + gid;
            #pragma unroll
            for (int nt = 0; nt < 8; nt++) {
                const float* C = c1f[mt][nt];
                int c0 = nh*64 + nt*8 + 2*tig;
                int s  = c0 >> 4, kk = c0 & 15;
                int off = s*16 + ((kk & 7) >> 1) * 4 + (kk >> 3) * 2;
                float b1a = sB1[c0], b1b = sB1[c0 + 1];
                float v0 = C[0] + b1a, v1 = C[1] + b1b;
                float v2 = C[2] + b1a, v3 = C[3] + b1b;
                v0 = __fdividef(v0, 1.0f + __expf(-v0));
                v1 = __fdividef(v1, 1.0f + __expf(-v1));
                v2 = __fdividef(v2, 1.0f + __expf(-v2));
                v3 = __fdividef(v3, 1.0f + __expf(-v3));
                *(__half2*)(smA2 + row0 * A2STR + off)       = __floats2half2_rn(v0, v1);
                *(__half2*)(smA2 + (row0 + 8) * A2STR + off) = __floats2half2_rn(v2, v3);
            }
        }
        __syncthreads();

        // ---------- layer 2: single pass, 8 k-steps ----------
        float c2f[2][8][4];
        #pragma unroll
        for (int a = 0; a < 2; a++)
            #pragma unroll
            for (int b = 0; b < 8; b++)
                #pragma unroll
                for (int c = 0; c < 4; c++) c2f[a][b][c] = 0.0f;

        #pragma unroll
        for (int s = 0; s < 8; s++) {
            uint2 a0 = *(const uint2*)(smA2 + (mg*32 + gid     ) * A2STR + s*16 + tig*4);
            uint2 a1 = *(const uint2*)(smA2 + (mg*32 + gid +  8) * A2STR + s*16 + tig*4);
            uint2 a2 = *(const uint2*)(smA2 + (mg*32 + gid + 16) * A2STR + s*16 + tig*4);
            uint2 a3 = *(const uint2*)(smA2 + (mg*32 + gid + 24) * A2STR + s*16 + tig*4);
            const __half* wrow = smW2 + (s*4 + tig) * WSTR;
            #pragma unroll
            for (int nt = 0; nt < 8; nt++) {
                uint2 b = *(const uint2*)(wrow + (nh*64 + nt*8 + gid) * 4);
                MMA_F16(c2f[0][nt], a0.x, a1.x, a0.y, a1.y, b.x, b.y);
                MMA_F16(c2f[1][nt], a2.x, a3.x, a2.y, a3.y, b.x, b.y);
            }
        }

        // ---------- epilogue: +b2, pair lanes, vector red scatter ----------
        #pragma unroll
        for (int mt = 0; mt < 2; mt++) {
            int r0 = mg*32 + mt*16 + gid;
            int r1 = r0 + 8;
            int d0 = sDst[r0], d1 = sDst[r1];
            bool ok0 = (ebase + r0) < E, ok1 = (ebase + r1) < E;
            #pragma unroll
            for (int nt = 0; nt < 8; nt++) {
                float* C = c2f[mt][nt];
                float q0 = __shfl_xor_sync(FULL, C[0], 1);
                float q1 = __shfl_xor_sync(FULL, C[1], 1);
                float q2 = __shfl_xor_sync(FULL, C[2], 1);
                float q3 = __shfl_xor_sync(FULL, C[3], 1);
                if ((tig & 1) == 0) {
                    int cb = nh*64 + nt*8 + 2*tig;
                    float4 bb = *(const float4*)(sB2 + cb);
                    if (ok0)
                        red_add_v4(g_acc + (size_t)d0 * HID + cb,
                                   C[0] + bb.x, C[1] + bb.y, q0 + bb.z, q1 + bb.w);
                } else {
                    int cb = nh*64 + nt*8 + 2*(tig - 1);
                    float4 bb = *(const float4*)(sB2 + cb);
                    if (ok1)
                        red_add_v4(g_acc + (size_t)d1 * HID + cb,
                                   q2 + bb.x, q3 + bb.y, C[2] + bb.z, C[3] + bb.w);
                }
            }
        }
    }
}

// ---------------- node output GEMM (validated, fp32) ----------------
__device__ __forceinline__ void ffma2(unsigned long long& d, unsigned long long a, unsigned long long b) {
    asm("fma.rn.f32x2 %0, %1, %2, %0;" : "+l"(d) : "l"(a), "l"(b));
}
__device__ __forceinline__ float hsum2(unsigned long long v) {
    float2 f = *reinterpret_cast<float2*>(&v);
    return f.x + f.y;
}

__global__ __launch_bounds__(128)
void node_kernel(const float* __restrict__ bo, float* __restrict__ out, int n_nodes)
{
    __shared__ float smem[4][8][HID];
    const int warp = threadIdx.x >> 5;
    const int lane = threadIdx.x & 31;
    const int nbase = blockIdx.x * 32 + warp * 8;
    float (*x)[HID] = smem[warp];

    float my_inv = 1.0f;
    if (lane < 8) {
        int n = nbase + lane;
        if (n < n_nodes) my_inv = 1.0f / fmaxf(g_deg[n], 1.0f);
    }
    #pragma unroll
    for (int e = 0; e < 8; e++) {
        float inv = __shfl_sync(FULL, my_inv, e);
        int n = nbase + e;
        float4 a = make_float4(0.f, 0.f, 0.f, 0.f);
        if (n < n_nodes) a = *(const float4*)(g_acc + (size_t)n * HID + 4 * lane);
        a.x *= inv; a.y *= inv; a.z *= inv; a.w *= inv;
        *(float4*)(&x[e][4 * lane]) = a;
    }
    __syncwarp();

    unsigned long long acc[8][4];
    #pragma unroll
    for (int e = 0; e < 8; e++)
        #pragma unroll
        for (int c = 0; c < 4; c++) acc[e][c] = 0ull;

    #pragma unroll 4
    for (int kp = 0; kp < HID / 2; kp++) {
        const float* wrow = g_Woi + (size_t)kp * (2 * HID) + 8 * lane;
        ulonglong2 wA = *(const ulonglong2*)(wrow);
        ulonglong2 wB = *(const ulonglong2*)(wrow + 4);
        #pragma unroll
        for (int e = 0; e < 8; e++) {
            unsigned long long m2 = *(const unsigned long long*)(&x[e][2 * kp]);
            ffma2(acc[e][0], m2, wA.x);
            ffma2(acc[e][1], m2, wA.y);
            ffma2(acc[e][2], m2, wB.x);
            ffma2(acc[e][3], m2, wB.y);
        }
    }
    float4 bb = *(const float4*)(bo + 4 * lane);
    #pragma unroll
    for (int e = 0; e < 8; e++) {
        int n = nbase + e;
        if (n < n_nodes) {
            float4 o;
            o.x = hsum2(acc[e][0]) + bb.x;
            o.y = hsum2(acc[e][1]) + bb.y;
            o.z = hsum2(acc[e][2]) + bb.z;
            o.w = hsum2(acc[e][3]) + bb.w;
            *(float4*)(out + (size_t)n * HID + 4 * lane) = o;
        }
    }
}

// ---------------- launch ----------------
extern "C" void kernel_launch(void* const* d_in, const int* in_sizes, int n_in,
                              void* d_out, int out_size) {
    const float* feat = (const float*)d_in[0];
    const float* pos  = (const float*)d_in[1];
    const int*   ei   = (const int*)d_in[2];
    const float* W1   = (const float*)d_in[3];
    const float* b1   = (const float*)d_in[4];
    const float* W2   = (const float*)d_in[5];
    const float* b2   = (const float*)d_in[6];
    const float* Wo   = (const float*)d_in[7];
    const float* bo   = (const float*)d_in[8];

    int n_nodes = in_sizes[0] / HID;
    int E = in_sizes[2] / 2;

    (void)cudaFuncSetAttribute(edge_kernel, cudaFuncAttributeMaxDynamicSharedMemorySize, SMEM_DYN);

    zero_kernel<<<512, 256>>>(n_nodes);
    prep_kernel<<<64, 256>>>(W1, W2, Wo);
    edge_kernel<<<148, 256, SMEM_DYN>>>(feat, pos, ei, b1, b2, E);

    int nblocks = (n_nodes + 31) / 32;
    node_kernel<<<nblocks, 128>>>(bo, (float*)d_out, n_nodes);
}